// round 3
// baseline (speedup 1.0000x reference)
#include <cuda_runtime.h>
#include <cuda_bf16.h>
#include <cstdint>

#define DIMV 768
#define TTOK 16384
#define HID  3072
#define NQKV 2304

// ---------------- device scratch (allocation-free rule: __device__ globals) -------------
__device__ __align__(256) __nv_bfloat16 g_act_hi[(size_t)TTOK * DIMV];
__device__ __align__(256) __nv_bfloat16 g_act_lo[(size_t)TTOK * DIMV];
__device__ __align__(256) float         g_qkv[(size_t)TTOK * NQKV];
__device__ __align__(256) float         g_y[(size_t)TTOK * DIMV];
__device__ __align__(256) __nv_bfloat16 g_h_hi[(size_t)TTOK * HID];
__device__ __align__(256) __nv_bfloat16 g_h_lo[(size_t)TTOK * HID];
__device__ __align__(256) __nv_bfloat16 g_wqkv_hi[(size_t)NQKV * DIMV];
__device__ __align__(256) __nv_bfloat16 g_wqkv_lo[(size_t)NQKV * DIMV];
__device__ __align__(256) __nv_bfloat16 g_w1_hi[(size_t)HID * DIMV];
__device__ __align__(256) __nv_bfloat16 g_w1_lo[(size_t)HID * DIMV];
__device__ __align__(256) __nv_bfloat16 g_w2_hi[(size_t)DIMV * HID];
__device__ __align__(256) __nv_bfloat16 g_w2_lo[(size_t)DIMV * HID];
__device__ __align__(256) float         g_qkvb[NQKV];

extern __shared__ char dyn_smem[];

// ---------------- PTX helpers (compute_103-baseline only; NO tcgen05) -------------------
__device__ __forceinline__ uint32_t smem_u32(const void* p) {
    uint32_t a;
    asm("{ .reg .u64 t; cvta.to.shared.u64 t, %1; cvt.u32.u64 %0, t; }" : "=r"(a) : "l"(p));
    return a;
}
__device__ __forceinline__ void cp16(uint32_t smaddr, const void* g) {
    asm volatile("cp.async.cg.shared.global [%0], [%1], 16;" :: "r"(smaddr), "l"(g) : "memory");
}
#define CP_COMMIT() asm volatile("cp.async.commit_group;" ::: "memory")
#define CP_WAIT(n)  asm volatile("cp.async.wait_group %0;" :: "n"(n) : "memory")

__device__ __forceinline__ void ldsm_x4(uint32_t* r, uint32_t addr) {
    asm volatile("ldmatrix.sync.aligned.m8n8.x4.shared.b16 {%0,%1,%2,%3}, [%4];"
                 : "=r"(r[0]), "=r"(r[1]), "=r"(r[2]), "=r"(r[3]) : "r"(addr));
}
__device__ __forceinline__ void ldsm_x2(uint32_t* r, uint32_t addr) {
    asm volatile("ldmatrix.sync.aligned.m8n8.x2.shared.b16 {%0,%1}, [%2];"
                 : "=r"(r[0]), "=r"(r[1]) : "r"(addr));
}
__device__ __forceinline__ void mma16816(float* c, const uint32_t* a, const uint32_t* b) {
    asm volatile("mma.sync.aligned.m16n8k16.row.col.f32.bf16.bf16.f32 "
                 "{%0,%1,%2,%3}, {%4,%5,%6,%7}, {%8,%9}, {%0,%1,%2,%3};"
                 : "+f"(c[0]), "+f"(c[1]), "+f"(c[2]), "+f"(c[3])
                 : "r"(a[0]), "r"(a[1]), "r"(a[2]), "r"(a[3]), "r"(b[0]), "r"(b[1]));
}

// ---------------- small helpers ----------------
__device__ __forceinline__ void split_store(float v, __nv_bfloat16* hi, __nv_bfloat16* lo, size_t idx) {
    __nv_bfloat16 h = __float2bfloat16(v);
    hi[idx] = h;
    lo[idx] = __float2bfloat16(v - __bfloat162float(h));
}
__device__ __forceinline__ float warp_sum(float v) {
    #pragma unroll
    for (int o = 16; o > 0; o >>= 1) v += __shfl_xor_sync(0xffffffffu, v, o);
    return v;
}

// ---------------- prep kernels ----------------
__global__ void split_kernel(const float* __restrict__ src, __nv_bfloat16* __restrict__ hi,
                             __nv_bfloat16* __restrict__ lo, int n) {
    for (int i = blockIdx.x * blockDim.x + threadIdx.x; i < n; i += gridDim.x * blockDim.x) {
        float v = src[i];
        __nv_bfloat16 h = __float2bfloat16(v);
        hi[i] = h;
        lo[i] = __float2bfloat16(v - __bfloat162float(h));
    }
}
__global__ void bias_concat_kernel(const float* __restrict__ bq, const float* __restrict__ bk,
                                   const float* __restrict__ bv) {
    int i = blockIdx.x * blockDim.x + threadIdx.x;
    if (i < NQKV) g_qkvb[i] = (i < 768) ? bq[i] : (i < 1536) ? bk[i - 768] : bv[i - 1536];
}

// ---------------- LN1: x -> split(layernorm(x)) ; warp per token ----------------
__global__ void ln1_kernel(const float* __restrict__ x, const float* __restrict__ g1,
                           const float* __restrict__ b1) {
    int wid = threadIdx.x >> 5, lid = threadIdx.x & 31;
    int tok = blockIdx.x * 8 + wid;
    const float* xr = x + (size_t)tok * DIMV;
    float xv[24];
    #pragma unroll
    for (int j = 0; j < 24; ++j) xv[j] = xr[lid + 32 * j];
    float s = 0.f;
    #pragma unroll
    for (int j = 0; j < 24; ++j) s += xv[j];
    float mean = warp_sum(s) * (1.0f / DIMV);
    float s2 = 0.f;
    #pragma unroll
    for (int j = 0; j < 24; ++j) { float d = xv[j] - mean; s2 += d * d; }
    float var = warp_sum(s2) * (1.0f / (DIMV - 1));
    float inv = g1[0] / (sqrtf(var) + 1e-6f);
    float bb = b1[0];
    size_t base = (size_t)tok * DIMV;
    #pragma unroll
    for (int j = 0; j < 24; ++j) {
        float n = (xv[j] - mean) * inv + bb;
        split_store(n, g_act_hi, g_act_lo, base + lid + 32 * j);
    }
}

// ---------------- attention + residual + LN2 (+split). block per group of 8 tokens ------
__global__ void attn_ln2_kernel(const float* __restrict__ x, const float* __restrict__ g2,
                                const float* __restrict__ b2) {
    float* ks = (float*)dyn_smem;           // 8*768
    float* vs = ks + 8 * DIMV;              // 8*768
    int tid = threadIdx.x;
    int wid = tid >> 5, lid = tid & 31;
    int t0 = blockIdx.x * 8;
    for (int i = tid; i < 8 * DIMV; i += 256) {
        int r = i / DIMV, c = i - r * DIMV;
        const float* row = g_qkv + (size_t)(t0 + r) * NQKV;
        ks[i] = row[768 + c];
        vs[i] = row[1536 + c];
    }
    __syncthreads();
    int h = wid;                            // 8 warps -> 8 query tokens
    const float* qr = g_qkv + (size_t)(t0 + h) * NQKV;
    float qv[24];
    #pragma unroll
    for (int j = 0; j < 24; ++j) qv[j] = qr[lid + 32 * j];
    float p[8];
    #pragma unroll
    for (int kk = 0; kk < 8; ++kk) {
        float acc = 0.f;
        const float* kr = ks + kk * DIMV;
        #pragma unroll
        for (int j = 0; j < 24; ++j) acc += qv[j] * kr[lid + 32 * j];
        p[kk] = acc;
    }
    #pragma unroll
    for (int kk = 0; kk < 8; ++kk) p[kk] = warp_sum(p[kk]) * 0.03608439182435161f; // 1/sqrt(768)
    float m = p[0];
    #pragma unroll
    for (int kk = 1; kk < 8; ++kk) m = fmaxf(m, p[kk]);
    float se = 0.f;
    #pragma unroll
    for (int kk = 0; kk < 8; ++kk) { p[kk] = __expf(p[kk] - m); se += p[kk]; }
    float rinv = 1.0f / se;
    #pragma unroll
    for (int kk = 0; kk < 8; ++kk) p[kk] *= rinv;
    const float* xr = x + (size_t)(t0 + h) * DIMV;
    float yv[24];
    #pragma unroll
    for (int j = 0; j < 24; ++j) {
        int d = lid + 32 * j;
        float a = 0.f;
        #pragma unroll
        for (int kk = 0; kk < 8; ++kk) a += p[kk] * vs[kk * DIMV + d];
        yv[j] = a + xr[d];
    }
    size_t base = (size_t)(t0 + h) * DIMV;
    #pragma unroll
    for (int j = 0; j < 24; ++j) g_y[base + lid + 32 * j] = yv[j];
    float s = 0.f;
    #pragma unroll
    for (int j = 0; j < 24; ++j) s += yv[j];
    float mean = warp_sum(s) * (1.0f / DIMV);
    float s2 = 0.f;
    #pragma unroll
    for (int j = 0; j < 24; ++j) { float d = yv[j] - mean; s2 += d * d; }
    float var = warp_sum(s2) * (1.0f / (DIMV - 1));
    float inv = g2[0] / (sqrtf(var) + 1e-6f);
    float bb = b2[0];
    #pragma unroll
    for (int j = 0; j < 24; ++j) {
        float n = (yv[j] - mean) * inv + bb;
        split_store(n, g_act_hi, g_act_lo, base + lid + 32 * j);
    }
}

// ---------------- mma.sync GEMM: 128x128 tile, BK=32, 3-stage cp.async, 3-term split ----
// smem per stage: 4 subtiles (Ahi, Alo, Bhi, Blo), each 128 rows x 32 bf16, row pitch 80B.
#define ST_SUB   10240              // 128*80
#define ST_SIZE  40960              // 4 subtiles
#define N_STAGE  3
#define GEMM_SMEM (N_STAGE * ST_SIZE)

// EPI 0: act @ wqkv^T + qkvb  -> g_qkv          (K=768,  N=2304)
// EPI 1: act @ w1^T + d1_b, gelu, split -> g_h  (K=768,  N=3072)
// EPI 2: h @ w2^T + d2_b + g_y -> outF          (K=3072, N=768)
template <int EPI>
__global__ void __launch_bounds__(256) gemm_k(const float* __restrict__ bias, float* __restrict__ outF) {
    constexpr int Kd = (EPI == 2) ? HID : DIMV;
    constexpr int NCH = Kd / 32;
    const __nv_bfloat16* Ahi = (EPI == 2) ? g_h_hi : g_act_hi;
    const __nv_bfloat16* Alo = (EPI == 2) ? g_h_lo : g_act_lo;
    const __nv_bfloat16* Bhi = (EPI == 0) ? g_wqkv_hi : (EPI == 1) ? g_w1_hi : g_w2_hi;
    const __nv_bfloat16* Blo = (EPI == 0) ? g_wqkv_lo : (EPI == 1) ? g_w1_lo : g_w2_lo;

    const int tid = threadIdx.x;
    const int lane = tid & 31, wid = tid >> 5;
    const int wm = wid >> 2, wn = wid & 3;      // 2 x 4 warp grid; warp tile 64 x 32
    const int bx = blockIdx.x, by = blockIdx.y;
    const uint32_t smb = smem_u32(dyn_smem);

    // async stage loader
    auto load_stage = [&](int c, int st) {
        uint32_t sb = smb + st * ST_SIZE;
        #pragma unroll
        for (int s = 0; s < 4; ++s) {
            const __nv_bfloat16* src = (s == 0) ? Ahi : (s == 1) ? Alo : (s == 2) ? Bhi : Blo;
            const int brow = (s < 2) ? by * 128 : bx * 128;
            #pragma unroll
            for (int j = 0; j < 2; ++j) {
                int id = tid + 256 * j;         // 0..511
                int r = id >> 2, q = id & 3;
                const __nv_bfloat16* g = src + (size_t)(brow + r) * Kd + c * 32 + q * 8;
                cp16(sb + s * ST_SUB + r * 80 + q * 16, g);
            }
        }
        CP_COMMIT();
    };

    float acc[4][4][4];
    #pragma unroll
    for (int mi = 0; mi < 4; ++mi)
        #pragma unroll
        for (int ni = 0; ni < 4; ++ni)
            #pragma unroll
            for (int r = 0; r < 4; ++r) acc[mi][ni][r] = 0.f;

    load_stage(0, 0);
    load_stage(1, 1);

    for (int c = 0; c < NCH; ++c) {
        const int st = c % N_STAGE;
        CP_WAIT(1);
        __syncthreads();
        if (c + 2 < NCH) load_stage(c + 2, (c + 2) % N_STAGE);

        const uint32_t sb = smb + st * ST_SIZE;
        #pragma unroll
        for (int ks = 0; ks < 2; ++ks) {
            uint32_t ahi[4][4], alo[4][4], bhi[4][2], blo[4][2];
            #pragma unroll
            for (int mi = 0; mi < 4; ++mi) {
                uint32_t ad = sb + (uint32_t)(wm * 64 + mi * 16 + (lane & 15)) * 80
                            + ks * 32 + (lane >> 4) * 16;
                ldsm_x4(ahi[mi], ad);
                ldsm_x4(alo[mi], ad + ST_SUB);
            }
            #pragma unroll
            for (int ni = 0; ni < 4; ++ni) {
                uint32_t bd = sb + 2 * ST_SUB + (uint32_t)(wn * 32 + ni * 8 + (lane & 7)) * 80
                            + ks * 32 + ((lane >> 3) & 1) * 16;
                ldsm_x2(bhi[ni], bd);
                ldsm_x2(blo[ni], bd + ST_SUB);
            }
            #pragma unroll
            for (int mi = 0; mi < 4; ++mi)
                #pragma unroll
                for (int ni = 0; ni < 4; ++ni) {
                    mma16816(acc[mi][ni], ahi[mi], bhi[ni]);
                    mma16816(acc[mi][ni], ahi[mi], blo[ni]);
                    mma16816(acc[mi][ni], alo[mi], bhi[ni]);
                }
        }
        __syncthreads();
    }
    CP_WAIT(0);

    // ---------------- epilogue ----------------
    const int r0 = lane >> 2, c0 = 2 * (lane & 3);
    #pragma unroll
    for (int mi = 0; mi < 4; ++mi) {
        #pragma unroll
        for (int hh = 0; hh < 2; ++hh) {
            const int grow = by * 128 + wm * 64 + mi * 16 + r0 + hh * 8;
            #pragma unroll
            for (int ni = 0; ni < 4; ++ni) {
                const int gcol = bx * 128 + wn * 32 + ni * 8 + c0;
                float v0 = acc[mi][ni][2 * hh + 0];
                float v1 = acc[mi][ni][2 * hh + 1];
                if (EPI == 0) {
                    float2 o;
                    o.x = v0 + g_qkvb[gcol];
                    o.y = v1 + g_qkvb[gcol + 1];
                    *(float2*)(g_qkv + (size_t)grow * NQKV + gcol) = o;
                } else if (EPI == 1) {
                    float u0 = v0 + bias[gcol];
                    float u1 = v1 + bias[gcol + 1];
                    float gl0 = 0.5f * u0 * (1.0f + erff(u0 * 0.70710678118654752440f));
                    float gl1 = 0.5f * u1 * (1.0f + erff(u1 * 0.70710678118654752440f));
                    __nv_bfloat16 h0 = __float2bfloat16(gl0);
                    __nv_bfloat16 h1 = __float2bfloat16(gl1);
                    __nv_bfloat16 l0 = __float2bfloat16(gl0 - __bfloat162float(h0));
                    __nv_bfloat16 l1 = __float2bfloat16(gl1 - __bfloat162float(h1));
                    size_t idx = (size_t)grow * HID + gcol;
                    *(__nv_bfloat162*)(g_h_hi + idx) = __nv_bfloat162(h0, h1);
                    *(__nv_bfloat162*)(g_h_lo + idx) = __nv_bfloat162(l0, l1);
                } else {
                    size_t idx = (size_t)grow * DIMV + gcol;
                    float2 res = *(const float2*)(g_y + idx);
                    float2 o;
                    o.x = v0 + bias[gcol] + res.x;
                    o.y = v1 + bias[gcol + 1] + res.y;
                    *(float2*)(outF + idx) = o;
                }
            }
        }
    }
}

// ---------------- launch ----------------
#define ATTN_SMEM (2 * 8 * DIMV * (int)sizeof(float))

extern "C" void kernel_launch(void* const* d_in, const int* in_sizes, int n_in,
                              void* d_out, int out_size) {
    const float* x    = (const float*)d_in[0];
    const float* wq_w = (const float*)d_in[1];
    const float* wq_b = (const float*)d_in[2];
    const float* wk_w = (const float*)d_in[3];
    const float* wk_b = (const float*)d_in[4];
    const float* wv_w = (const float*)d_in[5];
    const float* wv_b = (const float*)d_in[6];
    const float* d1_w = (const float*)d_in[7];
    const float* d1_b = (const float*)d_in[8];
    const float* d2_w = (const float*)d_in[9];
    const float* d2_b = (const float*)d_in[10];
    const float* g1   = (const float*)d_in[11];
    const float* b1   = (const float*)d_in[12];
    const float* g2   = (const float*)d_in[13];
    const float* b2   = (const float*)d_in[14];
    float* out = (float*)d_out;

    cudaFuncSetAttribute(gemm_k<0>, cudaFuncAttributeMaxDynamicSharedMemorySize, GEMM_SMEM);
    cudaFuncSetAttribute(gemm_k<1>, cudaFuncAttributeMaxDynamicSharedMemorySize, GEMM_SMEM);
    cudaFuncSetAttribute(gemm_k<2>, cudaFuncAttributeMaxDynamicSharedMemorySize, GEMM_SMEM);
    cudaFuncSetAttribute(attn_ln2_kernel, cudaFuncAttributeMaxDynamicSharedMemorySize, ATTN_SMEM);

    __nv_bfloat16 *wqkv_hi, *wqkv_lo, *w1_hi, *w1_lo, *w2_hi, *w2_lo;
    cudaGetSymbolAddress((void**)&wqkv_hi, g_wqkv_hi);
    cudaGetSymbolAddress((void**)&wqkv_lo, g_wqkv_lo);
    cudaGetSymbolAddress((void**)&w1_hi, g_w1_hi);
    cudaGetSymbolAddress((void**)&w1_lo, g_w1_lo);
    cudaGetSymbolAddress((void**)&w2_hi, g_w2_hi);
    cudaGetSymbolAddress((void**)&w2_lo, g_w2_lo);

    const int nW = DIMV * DIMV;
    split_kernel<<<1024, 256>>>(wq_w, wqkv_hi, wqkv_lo, nW);
    split_kernel<<<1024, 256>>>(wk_w, wqkv_hi + (size_t)768 * DIMV, wqkv_lo + (size_t)768 * DIMV, nW);
    split_kernel<<<1024, 256>>>(wv_w, wqkv_hi + (size_t)1536 * DIMV, wqkv_lo + (size_t)1536 * DIMV, nW);
    split_kernel<<<2048, 256>>>(d1_w, w1_hi, w1_lo, HID * DIMV);
    split_kernel<<<2048, 256>>>(d2_w, w2_hi, w2_lo, DIMV * HID);
    bias_concat_kernel<<<(NQKV + 255) / 256, 256>>>(wq_b, wk_b, wv_b);

    ln1_kernel<<<TTOK / 8, 256>>>(x, g1, b1);
    gemm_k<0><<<dim3(NQKV / 128, TTOK / 128), 256, GEMM_SMEM>>>(nullptr, nullptr);
    attn_ln2_kernel<<<TTOK / 8, 256, ATTN_SMEM>>>(x, g2, b2);
    gemm_k<1><<<dim3(HID / 128, TTOK / 128), 256, GEMM_SMEM>>>(d1_b, nullptr);
    gemm_k<2><<<dim3(DIMV / 128, TTOK / 128), 256, GEMM_SMEM>>>(d2_b, out);
}

// round 4
// speedup vs baseline: 1.1295x; 1.1295x over previous
#include <cuda_runtime.h>
#include <cuda_bf16.h>
#include <cstdint>

#define DIMV 768
#define TTOK 16384
#define HID  3072
#define NQKV 2304

// ---------------- device scratch (allocation-free rule: __device__ globals) -------------
__device__ __align__(256) __nv_bfloat16 g_act_hi[(size_t)TTOK * DIMV];
__device__ __align__(256) __nv_bfloat16 g_act_lo[(size_t)TTOK * DIMV];
__device__ __align__(256) float         g_qkv[(size_t)TTOK * NQKV];
__device__ __align__(256) float         g_y[(size_t)TTOK * DIMV];
__device__ __align__(256) __nv_bfloat16 g_h_hi[(size_t)TTOK * HID];
__device__ __align__(256) __nv_bfloat16 g_h_lo[(size_t)TTOK * HID];
__device__ __align__(256) __nv_bfloat16 g_wqkv_hi[(size_t)NQKV * DIMV];
__device__ __align__(256) __nv_bfloat16 g_wqkv_lo[(size_t)NQKV * DIMV];
__device__ __align__(256) __nv_bfloat16 g_w1_hi[(size_t)HID * DIMV];
__device__ __align__(256) __nv_bfloat16 g_w1_lo[(size_t)HID * DIMV];
__device__ __align__(256) __nv_bfloat16 g_w2_hi[(size_t)DIMV * HID];
__device__ __align__(256) __nv_bfloat16 g_w2_lo[(size_t)DIMV * HID];
__device__ __align__(256) float         g_qkvb[NQKV];

extern __shared__ char dyn_smem[];

// ---------------- PTX helpers (compute_103-baseline only) -------------------
__device__ __forceinline__ uint32_t smem_u32(const void* p) {
    uint32_t a;
    asm("{ .reg .u64 t; cvta.to.shared.u64 t, %1; cvt.u32.u64 %0, t; }" : "=r"(a) : "l"(p));
    return a;
}
__device__ __forceinline__ void cp16(uint32_t smaddr, const void* g) {
    asm volatile("cp.async.cg.shared.global [%0], [%1], 16;" :: "r"(smaddr), "l"(g) : "memory");
}
#define CP_COMMIT() asm volatile("cp.async.commit_group;" ::: "memory")
#define CP_WAIT(n)  asm volatile("cp.async.wait_group %0;" :: "n"(n) : "memory")

__device__ __forceinline__ void ldsm_x4(uint32_t* r, uint32_t addr) {
    asm volatile("ldmatrix.sync.aligned.m8n8.x4.shared.b16 {%0,%1,%2,%3}, [%4];"
                 : "=r"(r[0]), "=r"(r[1]), "=r"(r[2]), "=r"(r[3]) : "r"(addr));
}
__device__ __forceinline__ void ldsm_x2(uint32_t* r, uint32_t addr) {
    asm volatile("ldmatrix.sync.aligned.m8n8.x2.shared.b16 {%0,%1}, [%2];"
                 : "=r"(r[0]), "=r"(r[1]) : "r"(addr));
}
__device__ __forceinline__ void mma16816(float* c, const uint32_t* a, const uint32_t* b) {
    asm volatile("mma.sync.aligned.m16n8k16.row.col.f32.bf16.bf16.f32 "
                 "{%0,%1,%2,%3}, {%4,%5,%6,%7}, {%8,%9}, {%0,%1,%2,%3};"
                 : "+f"(c[0]), "+f"(c[1]), "+f"(c[2]), "+f"(c[3])
                 : "r"(a[0]), "r"(a[1]), "r"(a[2]), "r"(a[3]), "r"(b[0]), "r"(b[1]));
}

// ---------------- small helpers ----------------
__device__ __forceinline__ void split_store(float v, __nv_bfloat16* hi, __nv_bfloat16* lo, size_t idx) {
    __nv_bfloat16 h = __float2bfloat16(v);
    hi[idx] = h;
    lo[idx] = __float2bfloat16(v - __bfloat162float(h));
}
__device__ __forceinline__ float warp_sum(float v) {
    #pragma unroll
    for (int o = 16; o > 0; o >>= 1) v += __shfl_xor_sync(0xffffffffu, v, o);
    return v;
}

// ---------------- prep kernels (2 launches total so gemm1 lands at launch index 5) -----
__global__ void prep_qkv(const float* __restrict__ wq, const float* __restrict__ wk,
                         const float* __restrict__ wv, const float* __restrict__ bq,
                         const float* __restrict__ bk, const float* __restrict__ bv) {
    const int n = DIMV * DIMV;
    for (int i = blockIdx.x * blockDim.x + threadIdx.x; i < 3 * n + NQKV; i += gridDim.x * blockDim.x) {
        if (i < 3 * n) {
            int s = i / n, j = i - s * n;
            const float* w = (s == 0) ? wq : (s == 1) ? wk : wv;
            float v = w[j];
            __nv_bfloat16 h = __float2bfloat16(v);
            g_wqkv_hi[(size_t)s * n + j] = h;
            g_wqkv_lo[(size_t)s * n + j] = __float2bfloat16(v - __bfloat162float(h));
        } else {
            int j = i - 3 * n;
            g_qkvb[j] = (j < 768) ? bq[j] : (j < 1536) ? bk[j - 768] : bv[j - 1536];
        }
    }
}
__global__ void prep_mlp(const float* __restrict__ d1, const float* __restrict__ d2) {
    const int n = HID * DIMV;
    for (int i = blockIdx.x * blockDim.x + threadIdx.x; i < 2 * n; i += gridDim.x * blockDim.x) {
        if (i < n) {
            float v = d1[i];
            __nv_bfloat16 h = __float2bfloat16(v);
            g_w1_hi[i] = h;
            g_w1_lo[i] = __float2bfloat16(v - __bfloat162float(h));
        } else {
            int j = i - n;
            float v = d2[j];
            __nv_bfloat16 h = __float2bfloat16(v);
            g_w2_hi[j] = h;
            g_w2_lo[j] = __float2bfloat16(v - __bfloat162float(h));
        }
    }
}

// ---------------- LN1: x -> split(layernorm(x)) ; warp per token ----------------
__global__ void ln1_kernel(const float* __restrict__ x, const float* __restrict__ g1,
                           const float* __restrict__ b1) {
    int wid = threadIdx.x >> 5, lid = threadIdx.x & 31;
    int tok = blockIdx.x * 8 + wid;
    const float* xr = x + (size_t)tok * DIMV;
    float xv[24];
    #pragma unroll
    for (int j = 0; j < 24; ++j) xv[j] = xr[lid + 32 * j];
    float s = 0.f;
    #pragma unroll
    for (int j = 0; j < 24; ++j) s += xv[j];
    float mean = warp_sum(s) * (1.0f / DIMV);
    float s2 = 0.f;
    #pragma unroll
    for (int j = 0; j < 24; ++j) { float d = xv[j] - mean; s2 += d * d; }
    float var = warp_sum(s2) * (1.0f / (DIMV - 1));
    float inv = g1[0] / (sqrtf(var) + 1e-6f);
    float bb = b1[0];
    size_t base = (size_t)tok * DIMV;
    #pragma unroll
    for (int j = 0; j < 24; ++j) {
        float n = (xv[j] - mean) * inv + bb;
        split_store(n, g_act_hi, g_act_lo, base + lid + 32 * j);
    }
}

// ---------------- attention + residual + LN2 (+split). block per group of 8 tokens ------
__global__ void attn_ln2_kernel(const float* __restrict__ x, const float* __restrict__ g2,
                                const float* __restrict__ b2) {
    float* ks = (float*)dyn_smem;
    float* vs = ks + 8 * DIMV;
    int tid = threadIdx.x;
    int wid = tid >> 5, lid = tid & 31;
    int t0 = blockIdx.x * 8;
    for (int i = tid; i < 8 * DIMV; i += 256) {
        int r = i / DIMV, c = i - r * DIMV;
        const float* row = g_qkv + (size_t)(t0 + r) * NQKV;
        ks[i] = row[768 + c];
        vs[i] = row[1536 + c];
    }
    __syncthreads();
    int h = wid;
    const float* qr = g_qkv + (size_t)(t0 + h) * NQKV;
    float qv[24];
    #pragma unroll
    for (int j = 0; j < 24; ++j) qv[j] = qr[lid + 32 * j];
    float p[8];
    #pragma unroll
    for (int kk = 0; kk < 8; ++kk) {
        float acc = 0.f;
        const float* kr = ks + kk * DIMV;
        #pragma unroll
        for (int j = 0; j < 24; ++j) acc += qv[j] * kr[lid + 32 * j];
        p[kk] = acc;
    }
    #pragma unroll
    for (int kk = 0; kk < 8; ++kk) p[kk] = warp_sum(p[kk]) * 0.03608439182435161f;
    float m = p[0];
    #pragma unroll
    for (int kk = 1; kk < 8; ++kk) m = fmaxf(m, p[kk]);
    float se = 0.f;
    #pragma unroll
    for (int kk = 0; kk < 8; ++kk) { p[kk] = __expf(p[kk] - m); se += p[kk]; }
    float rinv = 1.0f / se;
    #pragma unroll
    for (int kk = 0; kk < 8; ++kk) p[kk] *= rinv;
    const float* xr = x + (size_t)(t0 + h) * DIMV;
    float yv[24];
    #pragma unroll
    for (int j = 0; j < 24; ++j) {
        int d = lid + 32 * j;
        float a = 0.f;
        #pragma unroll
        for (int kk = 0; kk < 8; ++kk) a += p[kk] * vs[kk * DIMV + d];
        yv[j] = a + xr[d];
    }
    size_t base = (size_t)(t0 + h) * DIMV;
    #pragma unroll
    for (int j = 0; j < 24; ++j) g_y[base + lid + 32 * j] = yv[j];
    float s = 0.f;
    #pragma unroll
    for (int j = 0; j < 24; ++j) s += yv[j];
    float mean = warp_sum(s) * (1.0f / DIMV);
    float s2 = 0.f;
    #pragma unroll
    for (int j = 0; j < 24; ++j) { float d = yv[j] - mean; s2 += d * d; }
    float var = warp_sum(s2) * (1.0f / (DIMV - 1));
    float inv = g2[0] / (sqrtf(var) + 1e-6f);
    float bb = b2[0];
    #pragma unroll
    for (int j = 0; j < 24; ++j) {
        float n = (yv[j] - mean) * inv + bb;
        split_store(n, g_act_hi, g_act_lo, base + lid + 32 * j);
    }
}

// ---------------- mma.sync GEMM: 128x256 tile, BK=32, 3-stage cp.async, 3-term split ----
// stage: Ahi(128x80B) Alo Bhi(256x80B) Blo = 61440 B
#define ST_A    10240
#define ST_B    20480
#define ST_SIZE 61440
#define N_STAGE 3
#define GEMM_SMEM (N_STAGE * ST_SIZE)

// EPI 0: act @ wqkv^T + qkvb  -> g_qkv          (K=768,  N=2304)
// EPI 1: act @ w1^T + d1_b, gelu, split -> g_h  (K=768,  N=3072)
// EPI 2: h @ w2^T + d2_b + g_y -> outF          (K=3072, N=768)
template <int EPI>
__global__ void __launch_bounds__(256) gemm_k(const float* __restrict__ bias, float* __restrict__ outF) {
    constexpr int Kd = (EPI == 2) ? HID : DIMV;
    constexpr int NCH = Kd / 32;
    const __nv_bfloat16* Ahi = (EPI == 2) ? g_h_hi : g_act_hi;
    const __nv_bfloat16* Alo = (EPI == 2) ? g_h_lo : g_act_lo;
    const __nv_bfloat16* Bhi = (EPI == 0) ? g_wqkv_hi : (EPI == 1) ? g_w1_hi : g_w2_hi;
    const __nv_bfloat16* Blo = (EPI == 0) ? g_wqkv_lo : (EPI == 1) ? g_w1_lo : g_w2_lo;

    const int tid = threadIdx.x;
    const int lane = tid & 31, wid = tid >> 5;
    const int wm = wid >> 2, wn = wid & 3;      // 2 x 4 warp grid; warp tile 64 x 64
    const int bx = blockIdx.x, by = blockIdx.y;
    const uint32_t smb = smem_u32(dyn_smem);

    auto load_stage = [&](int c, int st) {
        uint32_t sb = smb + st * ST_SIZE;
        #pragma unroll
        for (int s = 0; s < 2; ++s) {           // Ahi, Alo: 128 rows x 64B
            const __nv_bfloat16* src = s ? Alo : Ahi;
            #pragma unroll
            for (int j = 0; j < 2; ++j) {
                int id = tid + 256 * j;         // 0..511
                int r = id >> 2, q = id & 3;
                cp16(sb + s * ST_A + r * 80 + q * 16,
                     src + (size_t)(by * 128 + r) * Kd + c * 32 + q * 8);
            }
        }
        #pragma unroll
        for (int s = 0; s < 2; ++s) {           // Bhi, Blo: 256 rows x 64B
            const __nv_bfloat16* src = s ? Blo : Bhi;
            #pragma unroll
            for (int j = 0; j < 4; ++j) {
                int id = tid + 256 * j;         // 0..1023
                int r = id >> 2, q = id & 3;
                cp16(sb + 2 * ST_A + s * ST_B + r * 80 + q * 16,
                     src + (size_t)(bx * 256 + r) * Kd + c * 32 + q * 8);
            }
        }
        CP_COMMIT();
    };

    float acc[4][8][4];
    #pragma unroll
    for (int mi = 0; mi < 4; ++mi)
        #pragma unroll
        for (int ni = 0; ni < 8; ++ni)
            #pragma unroll
            for (int r = 0; r < 4; ++r) acc[mi][ni][r] = 0.f;

    load_stage(0, 0);
    load_stage(1, 1);

    for (int c = 0; c < NCH; ++c) {
        const int st = c % N_STAGE;
        CP_WAIT(1);
        __syncthreads();
        if (c + 2 < NCH) load_stage(c + 2, (c + 2) % N_STAGE);

        const uint32_t sb = smb + st * ST_SIZE;
        #pragma unroll
        for (int ks = 0; ks < 2; ++ks) {
            uint32_t bhi[8][2], blo[8][2];
            #pragma unroll
            for (int ni = 0; ni < 8; ++ni) {
                uint32_t bd = sb + 2 * ST_A + (uint32_t)(wn * 64 + ni * 8 + (lane & 7)) * 80
                            + ks * 32 + ((lane >> 3) & 1) * 16;
                ldsm_x2(bhi[ni], bd);
                ldsm_x2(blo[ni], bd + ST_B);
            }
            #pragma unroll
            for (int mi = 0; mi < 4; ++mi) {
                uint32_t ahi[4], alo[4];
                uint32_t ad = sb + (uint32_t)(wm * 64 + mi * 16 + (lane & 15)) * 80
                            + ks * 32 + (lane >> 4) * 16;
                ldsm_x4(ahi, ad);
                ldsm_x4(alo, ad + ST_A);
                #pragma unroll
                for (int ni = 0; ni < 8; ++ni) {
                    mma16816(acc[mi][ni], ahi, bhi[ni]);
                    mma16816(acc[mi][ni], ahi, blo[ni]);
                    mma16816(acc[mi][ni], alo, bhi[ni]);
                }
            }
        }
    }
    CP_WAIT(0);

    // ---------------- epilogue ----------------
    const int r0 = lane >> 2, c0 = 2 * (lane & 3);
    #pragma unroll
    for (int mi = 0; mi < 4; ++mi) {
        #pragma unroll
        for (int hh = 0; hh < 2; ++hh) {
            const int grow = by * 128 + wm * 64 + mi * 16 + r0 + hh * 8;
            #pragma unroll
            for (int ni = 0; ni < 8; ++ni) {
                const int gcol = bx * 256 + wn * 64 + ni * 8 + c0;
                float v0 = acc[mi][ni][2 * hh + 0];
                float v1 = acc[mi][ni][2 * hh + 1];
                if (EPI == 0) {
                    float2 o;
                    o.x = v0 + g_qkvb[gcol];
                    o.y = v1 + g_qkvb[gcol + 1];
                    *(float2*)(g_qkv + (size_t)grow * NQKV + gcol) = o;
                } else if (EPI == 1) {
                    float u0 = v0 + bias[gcol];
                    float u1 = v1 + bias[gcol + 1];
                    float gl0 = 0.5f * u0 * (1.0f + erff(u0 * 0.70710678118654752440f));
                    float gl1 = 0.5f * u1 * (1.0f + erff(u1 * 0.70710678118654752440f));
                    __nv_bfloat16 h0 = __float2bfloat16(gl0);
                    __nv_bfloat16 h1 = __float2bfloat16(gl1);
                    __nv_bfloat16 l0 = __float2bfloat16(gl0 - __bfloat162float(h0));
                    __nv_bfloat16 l1 = __float2bfloat16(gl1 - __bfloat162float(h1));
                    size_t idx = (size_t)grow * HID + gcol;
                    *(__nv_bfloat162*)(g_h_hi + idx) = __nv_bfloat162(h0, h1);
                    *(__nv_bfloat162*)(g_h_lo + idx) = __nv_bfloat162(l0, l1);
                } else {
                    size_t idx = (size_t)grow * DIMV + gcol;
                    float2 res = *(const float2*)(g_y + idx);
                    float2 o;
                    o.x = v0 + bias[gcol] + res.x;
                    o.y = v1 + bias[gcol + 1] + res.y;
                    *(float2*)(outF + idx) = o;
                }
            }
        }
    }
}

// ---------------- launch ----------------
#define ATTN_SMEM (2 * 8 * DIMV * (int)sizeof(float))

extern "C" void kernel_launch(void* const* d_in, const int* in_sizes, int n_in,
                              void* d_out, int out_size) {
    const float* x    = (const float*)d_in[0];
    const float* wq_w = (const float*)d_in[1];
    const float* wq_b = (const float*)d_in[2];
    const float* wk_w = (const float*)d_in[3];
    const float* wk_b = (const float*)d_in[4];
    const float* wv_w = (const float*)d_in[5];
    const float* wv_b = (const float*)d_in[6];
    const float* d1_w = (const float*)d_in[7];
    const float* d1_b = (const float*)d_in[8];
    const float* d2_w = (const float*)d_in[9];
    const float* d2_b = (const float*)d_in[10];
    const float* g1   = (const float*)d_in[11];
    const float* b1   = (const float*)d_in[12];
    const float* g2   = (const float*)d_in[13];
    const float* b2   = (const float*)d_in[14];
    float* out = (float*)d_out;

    cudaFuncSetAttribute(gemm_k<0>, cudaFuncAttributeMaxDynamicSharedMemorySize, GEMM_SMEM);
    cudaFuncSetAttribute(gemm_k<1>, cudaFuncAttributeMaxDynamicSharedMemorySize, GEMM_SMEM);
    cudaFuncSetAttribute(gemm_k<2>, cudaFuncAttributeMaxDynamicSharedMemorySize, GEMM_SMEM);
    cudaFuncSetAttribute(attn_ln2_kernel, cudaFuncAttributeMaxDynamicSharedMemorySize, ATTN_SMEM);

    // launch order chosen so ncu (-s 5 -c 1) profiles gemm_k<1>, the largest GEMM
    prep_qkv<<<2048, 256>>>(wq_w, wk_w, wv_w, wq_b, wk_b, wv_b);       // 0
    prep_mlp<<<4096, 256>>>(d1_w, d2_w);                               // 1
    ln1_kernel<<<TTOK / 8, 256>>>(x, g1, b1);                          // 2
    gemm_k<0><<<dim3(NQKV / 256, TTOK / 128), 256, GEMM_SMEM>>>(nullptr, nullptr);  // 3
    attn_ln2_kernel<<<TTOK / 8, 256, ATTN_SMEM>>>(x, g2, b2);          // 4
    gemm_k<1><<<dim3(HID / 256, TTOK / 128), 256, GEMM_SMEM>>>(d1_b, nullptr);      // 5 <- profiled
    gemm_k<2><<<dim3(DIMV / 256, TTOK / 128), 256, GEMM_SMEM>>>(d2_b, out);         // 6
}